// round 9
// baseline (speedup 1.0000x reference)
#include <cuda_runtime.h>
#include <cuda_bf16.h>
#include <cstdint>

// ---------------- problem constants ----------------
#define BHALF 4096
#define NROWS 8192
#define DDIM  1024
#define INVT  10.0f
#define Y_SCALE 14.4269504088896341f   // INVT * log2(e)

// ---------------- tiling ----------------
#define KC 64                 // K elems per pipeline stage
#define ROW_BYTES 144         // 64 bf16 = 128B + 16B pad
#define A_BYTES (128 * ROW_BYTES)          // 18432
#define STAGE_BYTES (2 * A_BYTES)          // 36864
#define NSTAGES 3
#define SMEM_TOTAL (NSTAGES * STAGE_BYTES) // 110592
#define NBLK 64               // 8192 / 128
#define NTILES (NBLK * (NBLK + 1) / 2)     // 2080 upper-triangle tiles
#define GRIDP 296             // persistent grid: 2 CTAs x 148 SMs

__device__ __align__(16) __nv_bfloat16 g_fn[NROWS * DDIM];  // normalized bf16 (16MB)
__device__ float g_rowsum[NROWS];
__device__ float g_pos[NROWS];

// ---------------------------------------------------------------------------
__device__ __forceinline__ float fexp2f(float y) {
    float t = y + 12582912.0f;
    int   i = __float_as_int(t);
    float f = y - (t - 12582912.0f);
    float p = 1.33335581e-3f;
    p = fmaf(p, f, 9.61812910e-3f);
    p = fmaf(p, f, 5.55041086e-2f);
    p = fmaf(p, f, 2.40226507e-1f);
    p = fmaf(p, f, 6.93147182e-1f);
    p = fmaf(p, f, 1.0f);
    return p * __int_as_float((i + (127 - 0x4B400000)) << 23);
}

// decode upper-triangle tile index -> (rb, cb), cb >= rb
__device__ __forceinline__ void decode_tile(int t, int& rb_o, int& cb_o) {
    int rb = (int)((129.0f - sqrtf(129.0f*129.0f - 8.0f*(float)t)) * 0.5f);
    if (rb > 63) rb = 63;
    if (rb < 0)  rb = 0;
    int off = rb*64 - rb*(rb-1)/2;
    while (off > t)                 { rb--; off = rb*64 - rb*(rb-1)/2; }
    while (off + (NBLK - rb) <= t)  { off += NBLK - rb; rb++; }
    rb_o = rb;
    cb_o = rb + (t - off);
}

// ---------------------------------------------------------------------------
// Kernel 1: row L2-normalize -> bf16 (one warp/row; contiguous 128B per lane)
// Also zeroes accumulators and out[0].
// ---------------------------------------------------------------------------
__global__ void __launch_bounds__(128) norm_kernel(const float* __restrict__ v1,
                                                   const float* __restrict__ v2,
                                                   float* __restrict__ out) {
    const int lane = threadIdx.x & 31;
    const int row  = blockIdx.x * 4 + (threadIdx.x >> 5);
    const float* src = (row < BHALF) ? (v1 + (size_t)row * DDIM)
                                     : (v2 + (size_t)(row - BHALF) * DDIM);
    const float4* src4 = reinterpret_cast<const float4*>(src) + lane * 8;
    float4 v[8];
    float ss = 0.0f;
    #pragma unroll
    for (int i = 0; i < 8; i++) {
        v[i] = src4[i];
        ss += v[i].x*v[i].x + v[i].y*v[i].y + v[i].z*v[i].z + v[i].w*v[i].w;
    }
    #pragma unroll
    for (int o = 16; o; o >>= 1) ss += __shfl_xor_sync(0xFFFFFFFFu, ss, o);
    float scale = 1.0f / fmaxf(sqrtf(ss), 1e-12f);

    uint4* dst = reinterpret_cast<uint4*>(g_fn + (size_t)row * DDIM) + lane * 4;
    #pragma unroll
    for (int k = 0; k < 4; k++) {
        const float4 &u = v[2*k], &w = v[2*k+1];
        __nv_bfloat162 h0, h1, h2, h3;
        h0.x = __float2bfloat16(u.x*scale); h0.y = __float2bfloat16(u.y*scale);
        h1.x = __float2bfloat16(u.z*scale); h1.y = __float2bfloat16(u.w*scale);
        h2.x = __float2bfloat16(w.x*scale); h2.y = __float2bfloat16(w.y*scale);
        h3.x = __float2bfloat16(w.z*scale); h3.y = __float2bfloat16(w.w*scale);
        uint4 o4;
        o4.x = *reinterpret_cast<unsigned*>(&h0);
        o4.y = *reinterpret_cast<unsigned*>(&h1);
        o4.z = *reinterpret_cast<unsigned*>(&h2);
        o4.w = *reinterpret_cast<unsigned*>(&h3);
        dst[k] = o4;
    }
    if (lane == 0) { g_rowsum[row] = 0.0f; g_pos[row] = 0.0f; }
    if (row == 0 && lane == 0) out[0] = 0.0f;
}

// ---------------------------------------------------------------------------
// PTX helpers
// ---------------------------------------------------------------------------
__device__ __forceinline__ void cp_async16(unsigned dst, const void* src) {
    asm volatile("cp.async.cg.shared.global [%0], [%1], 16;" :: "r"(dst), "l"(src) : "memory");
}
__device__ __forceinline__ void cp_commit() {
    asm volatile("cp.async.commit_group;" ::: "memory");
}
__device__ __forceinline__ void ldmatrix_x4(unsigned& r0, unsigned& r1,
                                            unsigned& r2, unsigned& r3, unsigned addr) {
    asm volatile("ldmatrix.sync.aligned.m8n8.x4.shared.b16 {%0,%1,%2,%3}, [%4];"
                 : "=r"(r0), "=r"(r1), "=r"(r2), "=r"(r3) : "r"(addr));
}
__device__ __forceinline__ void mma_bf16(float& d0, float& d1, float& d2, float& d3,
                                         unsigned a0, unsigned a1, unsigned a2, unsigned a3,
                                         unsigned b0, unsigned b1) {
    asm volatile("mma.sync.aligned.m16n8k16.row.col.f32.bf16.bf16.f32 "
                 "{%0,%1,%2,%3}, {%4,%5,%6,%7}, {%8,%9}, {%0,%1,%2,%3};"
                 : "+f"(d0), "+f"(d1), "+f"(d2), "+f"(d3)
                 : "r"(a0), "r"(a1), "r"(a2), "r"(a3), "r"(b0), "r"(b1));
}

// Load one K-chunk: A = rows of rb-block, B = rows of cb-block (both 128 x 64)
__device__ __forceinline__ void load_tiles(unsigned smem_base, int stage,
                                           int rb, int cb, int kc, int tid) {
    unsigned base = smem_base + stage * STAGE_BYTES;
    const __nv_bfloat16* fn = g_fn;
    #pragma unroll
    for (int it = 0; it < 8; it++) {
        int c   = tid + it * 256;          // 0..2047
        int isB = c >> 10;
        int cl  = c & 1023;
        int r   = cl >> 3;
        int p   = cl & 7;
        int srow = (isB ? cb : rb) * 128 + r;
        const void* src = fn + (size_t)srow * DDIM + kc * KC + p * 8;
        unsigned dst = base + isB * A_BYTES + r * ROW_BYTES + p * 16;
        cp_async16(dst, src);
    }
}

// ---------------------------------------------------------------------------
// Kernel 2: persistent symmetric fused sim GEMM + exp row/col sums
// grid GRIDP; each CTA processes tiles bid, bid+GRIDP, ... with a continuous
// cp.async pipeline across tile boundaries.
// ---------------------------------------------------------------------------
__global__ void __launch_bounds__(256, 2) simexp_kernel() {
    extern __shared__ char smem[];
    unsigned smem_base = (unsigned)__cvta_generic_to_shared(smem);

    const int tid  = threadIdx.x;
    const int lane = tid & 31;
    const int wid  = tid >> 5;
    const int wm   = wid & 3;          // warp row 0..3 (32 rows each)
    const int wn   = wid >> 2;         // warp col 0..1 (64 cols each)

    int t = blockIdx.x;
    if (t >= NTILES) return;
    const int nt    = (NTILES - t + GRIDP - 1) / GRIDP;   // tiles for this CTA
    const int total = nt * 16;                            // total K-chunks

    int rb, cb;
    decode_tile(t, rb, cb);

    // ldmatrix lane base addresses (stage-relative)
    const unsigned a_base = smem_base + (wm*32 + (lane & 15)) * ROW_BYTES + (lane >> 4) * 16;
    const unsigned b_base = smem_base + A_BYTES
                          + (wn*64 + (lane & 7) + ((lane >> 4) << 3)) * ROW_BYTES
                          + ((lane >> 3) & 1) * 16;

    const int rq = lane >> 2;      // 0..7
    const int cq = (lane & 3) * 2; // 0,2,4,6

    // prologue: chunks 0,1 of first tile
    load_tiles(smem_base, 0, rb, cb, 0, tid); cp_commit();
    load_tiles(smem_base, 1, rb, cb, 1, tid); cp_commit();

    int cur = 0;                   // continuous chunk counter
    for (int ti = 0; ti < nt; ti++) {
        // decode next tile (needed for cross-tile prefetch + end-of-tile swap)
        int rbn = 0, cbn = 0;
        const bool has_n = (ti + 1 < nt);
        if (has_n) decode_tile(t + GRIDP, rbn, cbn);

        const bool is_diag = (cb == rb);
        const bool is_pos  = (cb == rb + 32);

        float acc[2][8][4];
        #pragma unroll
        for (int mf = 0; mf < 2; mf++)
            #pragma unroll
            for (int j = 0; j < 8; j++)
                #pragma unroll
                for (int e = 0; e < 4; e++) acc[mf][j][e] = 0.0f;

        for (int kc = 0; kc < 16; kc++, cur++) {
            if (total - cur >= 2) asm volatile("cp.async.wait_group 1;" ::: "memory");
            else                  asm volatile("cp.async.wait_group 0;" ::: "memory");
            __syncthreads();
            const int q = cur + 2;
            if (q < total) {
                if (kc + 2 < 16) load_tiles(smem_base, q % NSTAGES, rb,  cb,  kc + 2,      tid);
                else             load_tiles(smem_base, q % NSTAGES, rbn, cbn, kc + 2 - 16, tid);
                cp_commit();
            }
            const unsigned sA = a_base + (cur % NSTAGES) * STAGE_BYTES;
            const unsigned sB = b_base + (cur % NSTAGES) * STAGE_BYTES;

            unsigned a[2][2][4];   // [buf][mf][frag] double-buffered across ks
            #pragma unroll
            for (int mf = 0; mf < 2; mf++)
                ldmatrix_x4(a[0][mf][0], a[0][mf][1], a[0][mf][2], a[0][mf][3],
                            sA + mf * (16 * ROW_BYTES));

            #pragma unroll
            for (int ks = 0; ks < 4; ks++) {
                const int ab = ks & 1;
                unsigned b[2][4];
                ldmatrix_x4(b[0][0], b[0][1], b[0][2], b[0][3], sB + ks * 32);
                if (ks < 3) {
                    #pragma unroll
                    for (int mf = 0; mf < 2; mf++)
                        ldmatrix_x4(a[ab^1][mf][0], a[ab^1][mf][1],
                                    a[ab^1][mf][2], a[ab^1][mf][3],
                                    sA + mf * (16 * ROW_BYTES) + (ks + 1) * 32);
                }
                #pragma unroll
                for (int nf = 0; nf < 4; nf++) {
                    const int bcur = nf & 1;
                    if (nf < 3)
                        ldmatrix_x4(b[bcur^1][0], b[bcur^1][1], b[bcur^1][2], b[bcur^1][3],
                                    sB + (nf + 1) * (16 * ROW_BYTES) + ks * 32);
                    #pragma unroll
                    for (int mf = 0; mf < 2; mf++) {
                        mma_bf16(acc[mf][2*nf][0],   acc[mf][2*nf][1],
                                 acc[mf][2*nf][2],   acc[mf][2*nf][3],
                                 a[ab][mf][0], a[ab][mf][1], a[ab][mf][2], a[ab][mf][3],
                                 b[bcur][0], b[bcur][1]);
                        mma_bf16(acc[mf][2*nf+1][0], acc[mf][2*nf+1][1],
                                 acc[mf][2*nf+1][2], acc[mf][2*nf+1][3],
                                 a[ab][mf][0], a[ab][mf][1], a[ab][mf][2], a[ab][mf][3],
                                 b[bcur][2], b[bcur][3]);
                    }
                }
            }
        }

        // ---------------- epilogue for tile (rb, cb) ----------------
        {
            float rs[2][2] = {{0.f,0.f},{0.f,0.f}};
            float cs[8][2];
            #pragma unroll
            for (int j = 0; j < 8; j++) { cs[j][0] = 0.f; cs[j][1] = 0.f; }

            #pragma unroll
            for (int mf = 0; mf < 2; mf++) {
                #pragma unroll
                for (int j = 0; j < 8; j++) {
                    #pragma unroll
                    for (int e = 0; e < 4; e++) {
                        float a  = acc[mf][j][e];
                        int r_local = wm*32 + mf*16 + rq + ((e & 2) ? 8 : 0);
                        int c_local = wn*64 + j*8 + cq + (e & 1);
                        float ev = fexp2f(a * Y_SCALE);
                        if (is_diag && r_local == c_local) ev = 0.0f;
                        rs[mf][e >> 1] += ev;
                        cs[j][e & 1]   += ev;
                        if (is_pos && r_local == c_local) {
                            float pv = a * INVT;
                            atomicAdd(&g_pos[rb*128 + r_local], pv);
                            atomicAdd(&g_pos[cb*128 + c_local], pv);
                        }
                    }
                }
            }

            #pragma unroll
            for (int mf = 0; mf < 2; mf++) {
                #pragma unroll
                for (int h = 0; h < 2; h++) {
                    float v = rs[mf][h];
                    v += __shfl_xor_sync(0xFFFFFFFFu, v, 1);
                    v += __shfl_xor_sync(0xFFFFFFFFu, v, 2);
                    if ((lane & 3) == 0)
                        atomicAdd(&g_rowsum[rb*128 + wm*32 + mf*16 + rq + h*8], v);
                }
            }

            if (!is_diag) {
                #pragma unroll
                for (int j = 0; j < 8; j++) {
                    #pragma unroll
                    for (int par = 0; par < 2; par++) {
                        float v = cs[j][par];
                        v += __shfl_xor_sync(0xFFFFFFFFu, v, 4);
                        v += __shfl_xor_sync(0xFFFFFFFFu, v, 8);
                        v += __shfl_xor_sync(0xFFFFFFFFu, v, 16);
                        if (lane < 4)
                            atomicAdd(&g_rowsum[cb*128 + wn*64 + j*8 + lane*2 + par], v);
                    }
                }
            }
        }

        t += GRIDP;
        rb = rbn; cb = cbn;
    }
}

// ---------------------------------------------------------------------------
// Kernel 3: loss partials -> atomicAdd into out (out zeroed by norm_kernel)
// ---------------------------------------------------------------------------
__global__ void __launch_bounds__(256) loss_kernel(float* __restrict__ out) {
    const int base = blockIdx.x * (NROWS / 32);
    float s = 0.0f;
    for (int i = threadIdx.x; i < NROWS / 32; i += 256) {
        int r = base + i;
        s += logf(g_rowsum[r]) - g_pos[r];
    }
    #pragma unroll
    for (int o = 16; o; o >>= 1) s += __shfl_xor_sync(0xFFFFFFFFu, s, o);
    __shared__ float red[8];
    if ((threadIdx.x & 31) == 0) red[threadIdx.x >> 5] = s;
    __syncthreads();
    if (threadIdx.x == 0) {
        float tot = red[0]+red[1]+red[2]+red[3]+red[4]+red[5]+red[6]+red[7];
        atomicAdd(out, tot * (1.0f / (float)NROWS));
    }
}

// ---------------------------------------------------------------------------
extern "C" void kernel_launch(void* const* d_in, const int* in_sizes, int n_in,
                              void* d_out, int out_size) {
    const float* v1 = (const float*)d_in[0];
    const float* v2 = (const float*)d_in[1];
    float* out = (float*)d_out;

    cudaFuncSetAttribute(simexp_kernel,
                         cudaFuncAttributeMaxDynamicSharedMemorySize, SMEM_TOTAL);

    norm_kernel<<<NROWS / 4, 128>>>(v1, v2, out);
    simexp_kernel<<<GRIDP, 256, SMEM_TOTAL>>>();
    loss_kernel<<<32, 256>>>(out);
}

// round 10
// speedup vs baseline: 1.2060x; 1.2060x over previous
#include <cuda_runtime.h>
#include <cuda_bf16.h>
#include <cstdint>

// ---------------- problem constants ----------------
#define BHALF 4096
#define NROWS 8192
#define DDIM  1024
#define INVT  10.0f
#define Y_SCALE 14.4269504088896341f   // INVT * log2(e)

// ---------------- tiling ----------------
#define KC 64                 // K elems per pipeline stage
#define ROW_BYTES 144         // 64 bf16 = 128B + 16B pad
#define A_BYTES (128 * ROW_BYTES)          // 18432
#define STAGE_BYTES (2 * A_BYTES)          // 36864
#define NSTAGES 3
#define SMEM_TOTAL (NSTAGES * STAGE_BYTES) // 110592
#define NBLK 64               // 8192 / 128
#define NTILES (NBLK * (NBLK + 1) / 2)     // 2080 upper-triangle tiles

__device__ __align__(16) __nv_bfloat16 g_fn[NROWS * DDIM];  // normalized bf16 (16MB)
__device__ float g_rowsum[NROWS];
__device__ float g_pos[NROWS];

// ---------------------------------------------------------------------------
__device__ __forceinline__ float fexp2f(float y) {
    float t = y + 12582912.0f;
    int   i = __float_as_int(t);
    float f = y - (t - 12582912.0f);
    float p = 1.33335581e-3f;
    p = fmaf(p, f, 9.61812910e-3f);
    p = fmaf(p, f, 5.55041086e-2f);
    p = fmaf(p, f, 2.40226507e-1f);
    p = fmaf(p, f, 6.93147182e-1f);
    p = fmaf(p, f, 1.0f);
    return p * __int_as_float((i + (127 - 0x4B400000)) << 23);
}

// ---------------------------------------------------------------------------
// Kernel 1: row L2-normalize -> bf16 (round-8 version; coalesced strided)
// Also zeroes accumulators and out[0].
// ---------------------------------------------------------------------------
__global__ void __launch_bounds__(128) norm_kernel(const float* __restrict__ v1,
                                                   const float* __restrict__ v2,
                                                   float* __restrict__ out) {
    const int lane = threadIdx.x & 31;
    const int row  = blockIdx.x * 4 + (threadIdx.x >> 5);
    const float* src = (row < BHALF) ? (v1 + (size_t)row * DDIM)
                                     : (v2 + (size_t)(row - BHALF) * DDIM);
    const float4* src4 = reinterpret_cast<const float4*>(src);
    float4 v[8];
    float ss = 0.0f;
    #pragma unroll
    for (int i = 0; i < 8; i++) {
        v[i] = src4[lane + i * 32];
        ss += v[i].x*v[i].x + v[i].y*v[i].y + v[i].z*v[i].z + v[i].w*v[i].w;
    }
    #pragma unroll
    for (int o = 16; o; o >>= 1) ss += __shfl_xor_sync(0xFFFFFFFFu, ss, o);
    float scale = 1.0f / fmaxf(sqrtf(ss), 1e-12f);

    __nv_bfloat162* dst = reinterpret_cast<__nv_bfloat162*>(g_fn + (size_t)row * DDIM);
    #pragma unroll
    for (int i = 0; i < 8; i++) {
        __nv_bfloat162 h0, h1;
        h0.x = __float2bfloat16(v[i].x * scale); h0.y = __float2bfloat16(v[i].y * scale);
        h1.x = __float2bfloat16(v[i].z * scale); h1.y = __float2bfloat16(v[i].w * scale);
        int idx = lane + i * 32;
        dst[idx * 2 + 0] = h0;
        dst[idx * 2 + 1] = h1;
    }
    if (lane == 0) { g_rowsum[row] = 0.0f; g_pos[row] = 0.0f; }
    if (row == 0 && lane == 0) out[0] = 0.0f;
}

// ---------------------------------------------------------------------------
// PTX helpers
// ---------------------------------------------------------------------------
__device__ __forceinline__ void cp_async16(unsigned dst, const void* src) {
    asm volatile("cp.async.cg.shared.global [%0], [%1], 16;" :: "r"(dst), "l"(src) : "memory");
}
__device__ __forceinline__ void cp_commit() {
    asm volatile("cp.async.commit_group;" ::: "memory");
}
__device__ __forceinline__ void ldmatrix_x4(unsigned& r0, unsigned& r1,
                                            unsigned& r2, unsigned& r3, unsigned addr) {
    asm volatile("ldmatrix.sync.aligned.m8n8.x4.shared.b16 {%0,%1,%2,%3}, [%4];"
                 : "=r"(r0), "=r"(r1), "=r"(r2), "=r"(r3) : "r"(addr));
}
__device__ __forceinline__ void mma_bf16(float& d0, float& d1, float& d2, float& d3,
                                         unsigned a0, unsigned a1, unsigned a2, unsigned a3,
                                         unsigned b0, unsigned b1) {
    asm volatile("mma.sync.aligned.m16n8k16.row.col.f32.bf16.bf16.f32 "
                 "{%0,%1,%2,%3}, {%4,%5,%6,%7}, {%8,%9}, {%0,%1,%2,%3};"
                 : "+f"(d0), "+f"(d1), "+f"(d2), "+f"(d3)
                 : "r"(a0), "r"(a1), "r"(a2), "r"(a3), "r"(b0), "r"(b1));
}

// Hoisted-address chunk load: per thread 4 A rows + 4 B rows, 16B each.
// pA/pB already point at this thread's (row, 16B-chunk) for chunk kc.
// Row stride per 'it' is 32 rows = 65536 B in gmem, 32*ROW_BYTES in smem.
__device__ __forceinline__ void load_chunk(unsigned dstbase,
                                           const char* pA, const char* pB) {
    #pragma unroll
    for (int it = 0; it < 4; it++)
        cp_async16(dstbase + it * (32 * ROW_BYTES), pA + (size_t)it * 65536);
    #pragma unroll
    for (int it = 0; it < 4; it++)
        cp_async16(dstbase + A_BYTES + it * (32 * ROW_BYTES), pB + (size_t)it * 65536);
}

// ---------------------------------------------------------------------------
// Kernel 2: symmetric fused sim GEMM + exp row/col sums (round-8 structure)
// grid NTILES (one 128x128 tile per CTA), 256 threads, warp tile 32x64
// ---------------------------------------------------------------------------
__global__ void __launch_bounds__(256, 2) simexp_kernel() {
    extern __shared__ char smem[];
    unsigned smem_base = (unsigned)__cvta_generic_to_shared(smem);

    const int tid  = threadIdx.x;
    const int lane = tid & 31;
    const int wid  = tid >> 5;
    const int wm   = wid & 3;          // warp row 0..3 (32 rows each)
    const int wn   = wid >> 2;         // warp col 0..1 (64 cols each)

    // decode upper-triangle tile index -> (rb, cb), cb >= rb
    const int t = blockIdx.x;
    int rb = (int)((129.0f - sqrtf(129.0f*129.0f - 8.0f*(float)t)) * 0.5f);
    if (rb > 63) rb = 63;
    if (rb < 0)  rb = 0;
    int off = rb*64 - rb*(rb-1)/2;
    while (off > t)                 { rb--; off = rb*64 - rb*(rb-1)/2; }
    while (off + (NBLK - rb) <= t)  { off += NBLK - rb; rb++; }
    const int cb = rb + (t - off);
    const bool is_diag = (cb == rb);
    const bool is_pos  = (cb == rb + 32);

    // ---- hoisted load addressing (per-thread affine pattern) ----
    const int rA   = tid >> 3;             // base row 0..31 (it adds 32)
    const int p16  = (tid & 7) * 16;       // 16B chunk within 128B row
    const char* gA = (const char*)g_fn
                   + ((size_t)(rb * 128 + rA) * DDIM) * 2 + p16;
    const char* gB = (const char*)g_fn
                   + ((size_t)(cb * 128 + rA) * DDIM) * 2 + p16;
    const unsigned ldst = smem_base + rA * ROW_BYTES + p16;

    // ldmatrix lane base addresses (stage-relative)
    const unsigned a_base = smem_base + (wm*32 + (lane & 15)) * ROW_BYTES + (lane >> 4) * 16;
    const unsigned b_base = smem_base + A_BYTES
                          + (wn*64 + (lane & 7) + ((lane >> 4) << 3)) * ROW_BYTES
                          + ((lane >> 3) & 1) * 16;

    float acc[2][8][4];
    #pragma unroll
    for (int mf = 0; mf < 2; mf++)
        #pragma unroll
        for (int j = 0; j < 8; j++)
            #pragma unroll
            for (int e = 0; e < 4; e++) acc[mf][j][e] = 0.0f;

    const int NCHUNK = DDIM / KC;    // 16
    load_chunk(ldst + 0*STAGE_BYTES, gA,       gB);       cp_commit();
    load_chunk(ldst + 1*STAGE_BYTES, gA + 128, gB + 128); cp_commit();

    for (int kc = 0; kc < NCHUNK; kc++) {
        if (kc < NCHUNK - 1) asm volatile("cp.async.wait_group 1;" ::: "memory");
        else                 asm volatile("cp.async.wait_group 0;" ::: "memory");
        __syncthreads();
        const unsigned sA = a_base + (kc % NSTAGES) * STAGE_BYTES;
        const unsigned sB = b_base + (kc % NSTAGES) * STAGE_BYTES;

        unsigned a[2][2][4];   // [buf][mf][frag] double-buffered across ks
        #pragma unroll
        for (int mf = 0; mf < 2; mf++)
            ldmatrix_x4(a[0][mf][0], a[0][mf][1], a[0][mf][2], a[0][mf][3],
                        sA + mf * (16 * ROW_BYTES));

        #pragma unroll
        for (int ks = 0; ks < 4; ks++) {
            const int ab = ks & 1;
            unsigned b[2][4];
            ldmatrix_x4(b[0][0], b[0][1], b[0][2], b[0][3], sB + ks * 32);
            if (ks < 3) {
                #pragma unroll
                for (int mf = 0; mf < 2; mf++)
                    ldmatrix_x4(a[ab^1][mf][0], a[ab^1][mf][1],
                                a[ab^1][mf][2], a[ab^1][mf][3],
                                sA + mf * (16 * ROW_BYTES) + (ks + 1) * 32);
            }
            #pragma unroll
            for (int nf = 0; nf < 4; nf++) {
                const int cur = nf & 1;
                if (nf < 3)
                    ldmatrix_x4(b[cur^1][0], b[cur^1][1], b[cur^1][2], b[cur^1][3],
                                sB + (nf + 1) * (16 * ROW_BYTES) + ks * 32);
                #pragma unroll
                for (int mf = 0; mf < 2; mf++) {
                    mma_bf16(acc[mf][2*nf][0],   acc[mf][2*nf][1],
                             acc[mf][2*nf][2],   acc[mf][2*nf][3],
                             a[ab][mf][0], a[ab][mf][1], a[ab][mf][2], a[ab][mf][3],
                             b[cur][0], b[cur][1]);
                    mma_bf16(acc[mf][2*nf+1][0], acc[mf][2*nf+1][1],
                             acc[mf][2*nf+1][2], acc[mf][2*nf+1][3],
                             a[ab][mf][0], a[ab][mf][1], a[ab][mf][2], a[ab][mf][3],
                             b[cur][2], b[cur][3]);
                }
            }
            // issue next prefetch AFTER the first ks block of MMAs so the
            // tensor pipe starts immediately after the barrier
            if (ks == 0 && kc + 2 < NCHUNK) {
                load_chunk(ldst + ((kc + 2) % NSTAGES) * STAGE_BYTES,
                           gA + (kc + 2) * 128, gB + (kc + 2) * 128);
                cp_commit();
            }
        }
    }

    // ---------------- epilogue ----------------
    float rs[2][2] = {{0.f,0.f},{0.f,0.f}};   // [mf][lo/hi] row sums
    float cs[8][2];                            // [j][parity] col sums
    #pragma unroll
    for (int j = 0; j < 8; j++) { cs[j][0] = 0.f; cs[j][1] = 0.f; }

    const int rq = lane >> 2;      // 0..7
    const int cq = (lane & 3) * 2; // 0,2,4,6

    #pragma unroll
    for (int mf = 0; mf < 2; mf++) {
        #pragma unroll
        for (int j = 0; j < 8; j++) {
            #pragma unroll
            for (int e = 0; e < 4; e++) {
                float a  = acc[mf][j][e];
                int r_local = wm*32 + mf*16 + rq + ((e & 2) ? 8 : 0);
                int c_local = wn*64 + j*8 + cq + (e & 1);
                float ev = fexp2f(a * Y_SCALE);
                if (is_diag && r_local == c_local) ev = 0.0f;
                rs[mf][e >> 1] += ev;
                cs[j][e & 1]   += ev;
                if (is_pos && r_local == c_local) {
                    float pv = a * INVT;
                    atomicAdd(&g_pos[rb*128 + r_local], pv);
                    atomicAdd(&g_pos[cb*128 + c_local], pv);
                }
            }
        }
    }

    // row sums: reduce over lane&3 (cols), write rows of rb block
    #pragma unroll
    for (int mf = 0; mf < 2; mf++) {
        #pragma unroll
        for (int h = 0; h < 2; h++) {
            float v = rs[mf][h];
            v += __shfl_xor_sync(0xFFFFFFFFu, v, 1);
            v += __shfl_xor_sync(0xFFFFFFFFu, v, 2);
            if ((lane & 3) == 0)
                atomicAdd(&g_rowsum[rb*128 + wm*32 + mf*16 + rq + h*8], v);
        }
    }

    // col sums: reduce over lane>>2 (rows), write rows of cb block (symmetry)
    if (!is_diag) {
        #pragma unroll
        for (int j = 0; j < 8; j++) {
            #pragma unroll
            for (int par = 0; par < 2; par++) {
                float v = cs[j][par];
                v += __shfl_xor_sync(0xFFFFFFFFu, v, 4);
                v += __shfl_xor_sync(0xFFFFFFFFu, v, 8);
                v += __shfl_xor_sync(0xFFFFFFFFu, v, 16);
                if (lane < 4)
                    atomicAdd(&g_rowsum[cb*128 + wn*64 + j*8 + lane*2 + par], v);
            }
        }
    }
}

// ---------------------------------------------------------------------------
// Kernel 3: loss partials -> atomicAdd into out (out zeroed by norm_kernel)
// ---------------------------------------------------------------------------
__global__ void __launch_bounds__(256) loss_kernel(float* __restrict__ out) {
    const int base = blockIdx.x * (NROWS / 32);
    float s = 0.0f;
    for (int i = threadIdx.x; i < NROWS / 32; i += 256) {
        int r = base + i;
        s += logf(g_rowsum[r]) - g_pos[r];
    }
    #pragma unroll
    for (int o = 16; o; o >>= 1) s += __shfl_xor_sync(0xFFFFFFFFu, s, o);
    __shared__ float red[8];
    if ((threadIdx.x & 31) == 0) red[threadIdx.x >> 5] = s;
    __syncthreads();
    if (threadIdx.x == 0) {
        float tot = red[0]+red[1]+red[2]+red[3]+red[4]+red[5]+red[6]+red[7];
        atomicAdd(out, tot * (1.0f / (float)NROWS));
    }
}

// ---------------------------------------------------------------------------
extern "C" void kernel_launch(void* const* d_in, const int* in_sizes, int n_in,
                              void* d_out, int out_size) {
    const float* v1 = (const float*)d_in[0];
    const float* v2 = (const float*)d_in[1];
    float* out = (float*)d_out;

    cudaFuncSetAttribute(simexp_kernel,
                         cudaFuncAttributeMaxDynamicSharedMemorySize, SMEM_TOTAL);

    norm_kernel<<<NROWS / 4, 128>>>(v1, v2, out);
    simexp_kernel<<<NTILES, 256, SMEM_TOTAL>>>();
    loss_kernel<<<32, 256>>>(out);
}

// round 11
// speedup vs baseline: 1.2261x; 1.0167x over previous
#include <cuda_runtime.h>
#include <cuda_bf16.h>
#include <cstdint>

// ---------------- problem constants ----------------
#define BHALF 4096
#define NROWS 8192
#define DDIM  1024
#define INVT  10.0f
#define Y_SCALE 14.4269504088896341f   // INVT * log2(e)

// ---------------- tiling ----------------
#define KC 64                 // K elems per pipeline stage
#define ROW_BYTES 144         // 64 bf16 = 128B + 16B pad
#define A_BYTES (128 * ROW_BYTES)          // 18432
#define STAGE_BYTES (2 * A_BYTES)          // 36864
#define NSTAGES 3
#define SMEM_TOTAL (NSTAGES * STAGE_BYTES) // 110592
#define NBLK 64               // 8192 / 128
#define NTILES (NBLK * (NBLK + 1) / 2)     // 2080 upper-triangle tiles

__device__ __align__(16) __nv_bfloat16 g_fn[NROWS * DDIM];  // normalized bf16 (16MB)
__device__ float g_rowsum[NROWS];
__device__ float g_pos[NROWS];

// ---------------------------------------------------------------------------
__device__ __forceinline__ float fexp2f(float y) {
    float t = y + 12582912.0f;
    int   i = __float_as_int(t);
    float f = y - (t - 12582912.0f);
    float p = 1.33335581e-3f;
    p = fmaf(p, f, 9.61812910e-3f);
    p = fmaf(p, f, 5.55041086e-2f);
    p = fmaf(p, f, 2.40226507e-1f);
    p = fmaf(p, f, 6.93147182e-1f);
    p = fmaf(p, f, 1.0f);
    return p * __int_as_float((i + (127 - 0x4B400000)) << 23);
}

// ---------------------------------------------------------------------------
// Kernel 1: row L2-normalize -> bf16; 32B coalesced loads, 16B stores.
// Also zeroes accumulators and out[0].
// ---------------------------------------------------------------------------
__global__ void __launch_bounds__(128) norm_kernel(const float* __restrict__ v1,
                                                   const float* __restrict__ v2,
                                                   float* __restrict__ out) {
    const int lane = threadIdx.x & 31;
    const int row  = blockIdx.x * 4 + (threadIdx.x >> 5);
    const float* src = (row < BHALF) ? (v1 + (size_t)row * DDIM)
                                     : (v2 + (size_t)(row - BHALF) * DDIM);
    const float4* src4 = reinterpret_cast<const float4*>(src);

    // lane handles float4 pairs (lane*2 + i*64, lane*2 + i*64 + 1), i=0..3
    float4 u[4], w[4];
    float ss = 0.0f;
    #pragma unroll
    for (int i = 0; i < 4; i++) {
        u[i] = src4[lane * 2 + i * 64];
        w[i] = src4[lane * 2 + i * 64 + 1];
        ss += u[i].x*u[i].x + u[i].y*u[i].y + u[i].z*u[i].z + u[i].w*u[i].w;
        ss += w[i].x*w[i].x + w[i].y*w[i].y + w[i].z*w[i].z + w[i].w*w[i].w;
    }
    #pragma unroll
    for (int o = 16; o; o >>= 1) ss += __shfl_xor_sync(0xFFFFFFFFu, ss, o);
    float scale = 1.0f / fmaxf(sqrtf(ss), 1e-12f);

    uint4* dst = reinterpret_cast<uint4*>(g_fn + (size_t)row * DDIM);
    #pragma unroll
    for (int i = 0; i < 4; i++) {
        __nv_bfloat162 h0, h1, h2, h3;
        h0.x = __float2bfloat16(u[i].x*scale); h0.y = __float2bfloat16(u[i].y*scale);
        h1.x = __float2bfloat16(u[i].z*scale); h1.y = __float2bfloat16(u[i].w*scale);
        h2.x = __float2bfloat16(w[i].x*scale); h2.y = __float2bfloat16(w[i].y*scale);
        h3.x = __float2bfloat16(w[i].z*scale); h3.y = __float2bfloat16(w[i].w*scale);
        uint4 o4;
        o4.x = *reinterpret_cast<unsigned*>(&h0);
        o4.y = *reinterpret_cast<unsigned*>(&h1);
        o4.z = *reinterpret_cast<unsigned*>(&h2);
        o4.w = *reinterpret_cast<unsigned*>(&h3);
        dst[lane + i * 32] = o4;
    }
    if (lane == 0) { g_rowsum[row] = 0.0f; g_pos[row] = 0.0f; }
    if (row == 0 && lane == 0) out[0] = 0.0f;
}

// ---------------------------------------------------------------------------
// PTX helpers
// ---------------------------------------------------------------------------
__device__ __forceinline__ void cp_async16(unsigned dst, const void* src) {
    asm volatile("cp.async.cg.shared.global [%0], [%1], 16;" :: "r"(dst), "l"(src) : "memory");
}
__device__ __forceinline__ void cp_commit() {
    asm volatile("cp.async.commit_group;" ::: "memory");
}
__device__ __forceinline__ void ldmatrix_x4(unsigned& r0, unsigned& r1,
                                            unsigned& r2, unsigned& r3, unsigned addr) {
    asm volatile("ldmatrix.sync.aligned.m8n8.x4.shared.b16 {%0,%1,%2,%3}, [%4];"
                 : "=r"(r0), "=r"(r1), "=r"(r2), "=r"(r3) : "r"(addr));
}
__device__ __forceinline__ void mma_bf16(float& d0, float& d1, float& d2, float& d3,
                                         unsigned a0, unsigned a1, unsigned a2, unsigned a3,
                                         unsigned b0, unsigned b1) {
    asm volatile("mma.sync.aligned.m16n8k16.row.col.f32.bf16.bf16.f32 "
                 "{%0,%1,%2,%3}, {%4,%5,%6,%7}, {%8,%9}, {%0,%1,%2,%3};"
                 : "+f"(d0), "+f"(d1), "+f"(d2), "+f"(d3)
                 : "r"(a0), "r"(a1), "r"(a2), "r"(a3), "r"(b0), "r"(b1));
}

// Half-chunk loads (A rows or B rows): 4 cp.async of 16B, hoisted pointers.
__device__ __forceinline__ void load_halfA(unsigned dstbase, const char* pA) {
    #pragma unroll
    for (int it = 0; it < 4; it++)
        cp_async16(dstbase + it * (32 * ROW_BYTES), pA + (size_t)it * 65536);
}
__device__ __forceinline__ void load_halfB(unsigned dstbase, const char* pB) {
    #pragma unroll
    for (int it = 0; it < 4; it++)
        cp_async16(dstbase + A_BYTES + it * (32 * ROW_BYTES), pB + (size_t)it * 65536);
}

// ---------------------------------------------------------------------------
// Kernel 2: symmetric fused sim GEMM + exp row/col sums
// grid NTILES (one 128x128 tile per CTA), 256 threads, warp tile 32x64
// ---------------------------------------------------------------------------
__global__ void __launch_bounds__(256, 2) simexp_kernel() {
    extern __shared__ char smem[];
    unsigned smem_base = (unsigned)__cvta_generic_to_shared(smem);

    const int tid  = threadIdx.x;
    const int lane = tid & 31;
    const int wid  = tid >> 5;
    const int wm   = wid & 3;          // warp row 0..3 (32 rows each)
    const int wn   = wid >> 2;         // warp col 0..1 (64 cols each)

    // decode upper-triangle tile index -> (rb, cb), cb >= rb
    const int t = blockIdx.x;
    int rb = (int)((129.0f - sqrtf(129.0f*129.0f - 8.0f*(float)t)) * 0.5f);
    if (rb > 63) rb = 63;
    if (rb < 0)  rb = 0;
    int off = rb*64 - rb*(rb-1)/2;
    while (off > t)                 { rb--; off = rb*64 - rb*(rb-1)/2; }
    while (off + (NBLK - rb) <= t)  { off += NBLK - rb; rb++; }
    const int cb = rb + (t - off);
    const bool is_diag = (cb == rb);
    const bool is_pos  = (cb == rb + 32);

    // ---- hoisted load addressing (per-thread affine pattern) ----
    const int rA   = tid >> 3;             // base row 0..31 (it adds 32)
    const int p16  = (tid & 7) * 16;       // 16B chunk within 128B row
    const char* gA = (const char*)g_fn
                   + ((size_t)(rb * 128 + rA) * DDIM) * 2 + p16;
    const char* gB = (const char*)g_fn
                   + ((size_t)(cb * 128 + rA) * DDIM) * 2 + p16;
    const unsigned ldst = smem_base + rA * ROW_BYTES + p16;

    // ldmatrix lane base addresses (stage-relative)
    const unsigned a_base = smem_base + (wm*32 + (lane & 15)) * ROW_BYTES + (lane >> 4) * 16;
    const unsigned b_base = smem_base + A_BYTES
                          + (wn*64 + (lane & 7) + ((lane >> 4) << 3)) * ROW_BYTES
                          + ((lane >> 3) & 1) * 16;

    float acc[2][8][4];
    #pragma unroll
    for (int mf = 0; mf < 2; mf++)
        #pragma unroll
        for (int j = 0; j < 8; j++)
            #pragma unroll
            for (int e = 0; e < 4; e++) acc[mf][j][e] = 0.0f;

    const int NCHUNK = DDIM / KC;    // 16
    load_halfA(ldst + 0*STAGE_BYTES, gA);
    load_halfB(ldst + 0*STAGE_BYTES, gB);       cp_commit();
    load_halfA(ldst + 1*STAGE_BYTES, gA + 128);
    load_halfB(ldst + 1*STAGE_BYTES, gB + 128); cp_commit();

    for (int kc = 0; kc < NCHUNK; kc++) {
        if (kc < NCHUNK - 1) asm volatile("cp.async.wait_group 1;" ::: "memory");
        else                 asm volatile("cp.async.wait_group 0;" ::: "memory");
        __syncthreads();
        const unsigned sA = a_base + (kc % NSTAGES) * STAGE_BYTES;
        const unsigned sB = b_base + (kc % NSTAGES) * STAGE_BYTES;
        const unsigned pdst = ldst + ((kc + 2) % NSTAGES) * STAGE_BYTES;
        const bool     pf   = (kc + 2 < NCHUNK);

        unsigned a[2][2][4];   // [buf][mf][frag] double-buffered across ks
        #pragma unroll
        for (int mf = 0; mf < 2; mf++)
            ldmatrix_x4(a[0][mf][0], a[0][mf][1], a[0][mf][2], a[0][mf][3],
                        sA + mf * (16 * ROW_BYTES));

        #pragma unroll
        for (int ks = 0; ks < 4; ks++) {
            const int ab = ks & 1;
            unsigned b[2][4];
            ldmatrix_x4(b[0][0], b[0][1], b[0][2], b[0][3], sB + ks * 32);
            if (ks < 3) {
                #pragma unroll
                for (int mf = 0; mf < 2; mf++)
                    ldmatrix_x4(a[ab^1][mf][0], a[ab^1][mf][1],
                                a[ab^1][mf][2], a[ab^1][mf][3],
                                sA + mf * (16 * ROW_BYTES) + (ks + 1) * 32);
            }
            #pragma unroll
            for (int nf = 0; nf < 4; nf++) {
                const int cur = nf & 1;
                if (nf < 3)
                    ldmatrix_x4(b[cur^1][0], b[cur^1][1], b[cur^1][2], b[cur^1][3],
                                sB + (nf + 1) * (16 * ROW_BYTES) + ks * 32);
                #pragma unroll
                for (int mf = 0; mf < 2; mf++) {
                    mma_bf16(acc[mf][2*nf][0],   acc[mf][2*nf][1],
                             acc[mf][2*nf][2],   acc[mf][2*nf][3],
                             a[ab][mf][0], a[ab][mf][1], a[ab][mf][2], a[ab][mf][3],
                             b[cur][0], b[cur][1]);
                    mma_bf16(acc[mf][2*nf+1][0], acc[mf][2*nf+1][1],
                             acc[mf][2*nf+1][2], acc[mf][2*nf+1][3],
                             a[ab][mf][0], a[ab][mf][1], a[ab][mf][2], a[ab][mf][3],
                             b[cur][2], b[cur][3]);
                }
            }
            // spread the next-chunk prefetch: A-half after ks=0, B-half after ks=1
            if (ks == 0 && pf) load_halfA(pdst, gA + (kc + 2) * 128);
            if (ks == 1 && pf) { load_halfB(pdst, gB + (kc + 2) * 128); cp_commit(); }
        }
    }

    // ---------------- epilogue ----------------
    float rs[2][2] = {{0.f,0.f},{0.f,0.f}};   // [mf][lo/hi] row sums
    float cs[8][2];                            // [j][parity] col sums
    #pragma unroll
    for (int j = 0; j < 8; j++) { cs[j][0] = 0.f; cs[j][1] = 0.f; }

    const int rq = lane >> 2;      // 0..7
    const int cq = (lane & 3) * 2; // 0,2,4,6

    #pragma unroll
    for (int mf = 0; mf < 2; mf++) {
        #pragma unroll
        for (int j = 0; j < 8; j++) {
            #pragma unroll
            for (int e = 0; e < 4; e++) {
                float a  = acc[mf][j][e];
                int r_local = wm*32 + mf*16 + rq + ((e & 2) ? 8 : 0);
                int c_local = wn*64 + j*8 + cq + (e & 1);
                float ev = fexp2f(a * Y_SCALE);
                if (is_diag && r_local == c_local) ev = 0.0f;
                rs[mf][e >> 1] += ev;
                cs[j][e & 1]   += ev;
                if (is_pos && r_local == c_local) {
                    float pv = a * INVT;
                    atomicAdd(&g_pos[rb*128 + r_local], pv);
                    atomicAdd(&g_pos[cb*128 + c_local], pv);
                }
            }
        }
    }

    // row sums: reduce over lane&3 (cols), write rows of rb block
    #pragma unroll
    for (int mf = 0; mf < 2; mf++) {
        #pragma unroll
        for (int h = 0; h < 2; h++) {
            float v = rs[mf][h];
            v += __shfl_xor_sync(0xFFFFFFFFu, v, 1);
            v += __shfl_xor_sync(0xFFFFFFFFu, v, 2);
            if ((lane & 3) == 0)
                atomicAdd(&g_rowsum[rb*128 + wm*32 + mf*16 + rq + h*8], v);
        }
    }

    // col sums: reduce over lane>>2 (rows), write rows of cb block (symmetry)
    if (!is_diag) {
        #pragma unroll
        for (int j = 0; j < 8; j++) {
            #pragma unroll
            for (int par = 0; par < 2; par++) {
                float v = cs[j][par];
                v += __shfl_xor_sync(0xFFFFFFFFu, v, 4);
                v += __shfl_xor_sync(0xFFFFFFFFu, v, 8);
                v += __shfl_xor_sync(0xFFFFFFFFu, v, 16);
                if (lane < 4)
                    atomicAdd(&g_rowsum[cb*128 + wn*64 + j*8 + lane*2 + par], v);
            }
        }
    }
}

// ---------------------------------------------------------------------------
// Kernel 3: loss partials -> atomicAdd into out (out zeroed by norm_kernel)
// ---------------------------------------------------------------------------
__global__ void __launch_bounds__(256) loss_kernel(float* __restrict__ out) {
    const int base = blockIdx.x * (NROWS / 32);
    float s = 0.0f;
    for (int i = threadIdx.x; i < NROWS / 32; i += 256) {
        int r = base + i;
        s += logf(g_rowsum[r]) - g_pos[r];
    }
    #pragma unroll
    for (int o = 16; o; o >>= 1) s += __shfl_xor_sync(0xFFFFFFFFu, s, o);
    __shared__ float red[8];
    if ((threadIdx.x & 31) == 0) red[threadIdx.x >> 5] = s;
    __syncthreads();
    if (threadIdx.x == 0) {
        float tot = red[0]+red[1]+red[2]+red[3]+red[4]+red[5]+red[6]+red[7];
        atomicAdd(out, tot * (1.0f / (float)NROWS));
    }
}

// ---------------------------------------------------------------------------
extern "C" void kernel_launch(void* const* d_in, const int* in_sizes, int n_in,
                              void* d_out, int out_size) {
    const float* v1 = (const float*)d_in[0];
    const float* v2 = (const float*)d_in[1];
    float* out = (float*)d_out;

    cudaFuncSetAttribute(simexp_kernel,
                         cudaFuncAttributeMaxDynamicSharedMemorySize, SMEM_TOTAL);

    norm_kernel<<<NROWS / 4, 128>>>(v1, v2, out);
    simexp_kernel<<<NTILES, 256, SMEM_TOTAL>>>();
    loss_kernel<<<32, 256>>>(out);
}

// round 12
// speedup vs baseline: 1.4031x; 1.1443x over previous
#include <cuda_runtime.h>
#include <cuda_bf16.h>
#include <cstdint>

// ---------------- problem constants ----------------
#define BHALF 4096
#define NROWS 8192
#define DDIM  1024
#define INVT  10.0f
#define Y_SCALE 14.4269504088896341f   // INVT * log2(e)

// ---------------- tiling ----------------
#define KC 64                 // K elems per pipeline stage
#define ROW_BYTES 144         // 64 bf16 = 128B + 16B pad
#define A_BYTES (128 * ROW_BYTES)          // 18432
#define STAGE_BYTES (2 * A_BYTES)          // 36864
#define NSTAGES 3
#define SMEM_TOTAL (NSTAGES * STAGE_BYTES) // 110592
#define NBLK 64               // 8192 / 128
#define NTILES (NBLK * (NBLK + 1) / 2)     // 2080 upper-triangle tiles
// job packing: 8 double jobs (tiles 1..16) + 2064 singles = 2072 = 296*7
#define NJOBS 2072

__device__ __align__(16) __nv_bfloat16 g_fn[NROWS * DDIM];  // normalized bf16 (16MB)
__device__ float g_rowsum[NROWS];
__device__ float g_pos[NROWS];

// ---------------------------------------------------------------------------
__device__ __forceinline__ float fexp2f(float y) {
    float t = y + 12582912.0f;
    int   i = __float_as_int(t);
    float f = y - (t - 12582912.0f);
    float p = 1.33335581e-3f;
    p = fmaf(p, f, 9.61812910e-3f);
    p = fmaf(p, f, 5.55041086e-2f);
    p = fmaf(p, f, 2.40226507e-1f);
    p = fmaf(p, f, 6.93147182e-1f);
    p = fmaf(p, f, 1.0f);
    return p * __int_as_float((i + (127 - 0x4B400000)) << 23);
}

// ---------------------------------------------------------------------------
// Kernel 1: row L2-normalize -> bf16; also zeroes accumulators and out[0].
// ---------------------------------------------------------------------------
__global__ void __launch_bounds__(128) norm_kernel(const float* __restrict__ v1,
                                                   const float* __restrict__ v2,
                                                   float* __restrict__ out) {
    const int lane = threadIdx.x & 31;
    const int row  = blockIdx.x * 4 + (threadIdx.x >> 5);
    const float* src = (row < BHALF) ? (v1 + (size_t)row * DDIM)
                                     : (v2 + (size_t)(row - BHALF) * DDIM);
    const float4* src4 = reinterpret_cast<const float4*>(src);

    float4 u[4], w[4];
    float ss = 0.0f;
    #pragma unroll
    for (int i = 0; i < 4; i++) {
        u[i] = src4[lane * 2 + i * 64];
        w[i] = src4[lane * 2 + i * 64 + 1];
        ss += u[i].x*u[i].x + u[i].y*u[i].y + u[i].z*u[i].z + u[i].w*u[i].w;
        ss += w[i].x*w[i].x + w[i].y*w[i].y + w[i].z*w[i].z + w[i].w*w[i].w;
    }
    #pragma unroll
    for (int o = 16; o; o >>= 1) ss += __shfl_xor_sync(0xFFFFFFFFu, ss, o);
    float scale = 1.0f / fmaxf(sqrtf(ss), 1e-12f);

    uint4* dst = reinterpret_cast<uint4*>(g_fn + (size_t)row * DDIM);
    #pragma unroll
    for (int i = 0; i < 4; i++) {
        __nv_bfloat162 h0, h1, h2, h3;
        h0.x = __float2bfloat16(u[i].x*scale); h0.y = __float2bfloat16(u[i].y*scale);
        h1.x = __float2bfloat16(u[i].z*scale); h1.y = __float2bfloat16(u[i].w*scale);
        h2.x = __float2bfloat16(w[i].x*scale); h2.y = __float2bfloat16(w[i].y*scale);
        h3.x = __float2bfloat16(w[i].z*scale); h3.y = __float2bfloat16(w[i].w*scale);
        uint4 o4;
        o4.x = *reinterpret_cast<unsigned*>(&h0);
        o4.y = *reinterpret_cast<unsigned*>(&h1);
        o4.z = *reinterpret_cast<unsigned*>(&h2);
        o4.w = *reinterpret_cast<unsigned*>(&h3);
        dst[lane + i * 32] = o4;
    }
    if (lane == 0) { g_rowsum[row] = 0.0f; g_pos[row] = 0.0f; }
    if (row == 0 && lane == 0) out[0] = 0.0f;
}

// ---------------------------------------------------------------------------
// PTX helpers
// ---------------------------------------------------------------------------
__device__ __forceinline__ void cp_async16(unsigned dst, const void* src) {
    asm volatile("cp.async.cg.shared.global [%0], [%1], 16;" :: "r"(dst), "l"(src) : "memory");
}
__device__ __forceinline__ void cp_commit() {
    asm volatile("cp.async.commit_group;" ::: "memory");
}
__device__ __forceinline__ void ldmatrix_x4(unsigned& r0, unsigned& r1,
                                            unsigned& r2, unsigned& r3, unsigned addr) {
    asm volatile("ldmatrix.sync.aligned.m8n8.x4.shared.b16 {%0,%1,%2,%3}, [%4];"
                 : "=r"(r0), "=r"(r1), "=r"(r2), "=r"(r3) : "r"(addr));
}
__device__ __forceinline__ void mma_bf16(float& d0, float& d1, float& d2, float& d3,
                                         unsigned a0, unsigned a1, unsigned a2, unsigned a3,
                                         unsigned b0, unsigned b1) {
    asm volatile("mma.sync.aligned.m16n8k16.row.col.f32.bf16.bf16.f32 "
                 "{%0,%1,%2,%3}, {%4,%5,%6,%7}, {%8,%9}, {%0,%1,%2,%3};"
                 : "+f"(d0), "+f"(d1), "+f"(d2), "+f"(d3)
                 : "r"(a0), "r"(a1), "r"(a2), "r"(a3), "r"(b0), "r"(b1));
}

// Half-chunk loads (A rows or B rows): 4 cp.async of 16B, hoisted pointers.
__device__ __forceinline__ void load_halfA(unsigned dstbase, const char* pA) {
    #pragma unroll
    for (int it = 0; it < 4; it++)
        cp_async16(dstbase + it * (32 * ROW_BYTES), pA + (size_t)it * 65536);
}
__device__ __forceinline__ void load_halfB(unsigned dstbase, const char* pB) {
    #pragma unroll
    for (int it = 0; it < 4; it++)
        cp_async16(dstbase + A_BYTES + it * (32 * ROW_BYTES), pB + (size_t)it * 65536);
}

// ---------------------------------------------------------------------------
// Kernel 2: symmetric fused sim GEMM + exp row/col sums.
// grid NJOBS: bid<8 = double job (rb=0, cb=1+2*bid, 2 sub-tiles);
// else single job over remapped tile index. 256 threads, warp tile 32x64.
// ---------------------------------------------------------------------------
__global__ void __launch_bounds__(256, 2) simexp_kernel() {
    extern __shared__ char smem[];
    unsigned smem_base = (unsigned)__cvta_generic_to_shared(smem);

    const int tid  = threadIdx.x;
    const int lane = tid & 31;
    const int wid  = tid >> 5;
    const int wm   = wid & 3;          // warp row 0..3 (32 rows each)
    const int wn   = wid >> 2;         // warp col 0..1 (64 cols each)

    // ---- job decode ----
    const int bid = blockIdx.x;
    int rb, cb0, nsub;
    if (bid < 8) {
        rb = 0; cb0 = 1 + bid * 2; nsub = 2;
    } else {
        int s = bid - 8;
        int t = (s == 0) ? 0 : 16 + s;       // tiles {0} U {17..2079}
        int r = (int)((129.0f - sqrtf(129.0f*129.0f - 8.0f*(float)t)) * 0.5f);
        if (r > 63) r = 63;
        if (r < 0)  r = 0;
        int off = r*64 - r*(r-1)/2;
        while (off > t)                { r--; off = r*64 - r*(r-1)/2; }
        while (off + (NBLK - r) <= t)  { off += NBLK - r; r++; }
        rb = r; cb0 = r + (t - off); nsub = 1;
    }

    // ---- hoisted per-thread load addressing ----
    const int rA   = tid >> 3;             // base row 0..31 (it adds 32)
    const int p16  = (tid & 7) * 16;       // 16B chunk within 128B row
    const char* gA = (const char*)g_fn
                   + ((size_t)(rb * 128 + rA) * DDIM) * 2 + p16;
    const unsigned ldst = smem_base + rA * ROW_BYTES + p16;

    // ldmatrix lane base addresses (stage-relative)
    const unsigned a_base = smem_base + (wm*32 + (lane & 15)) * ROW_BYTES + (lane >> 4) * 16;
    const unsigned b_base = smem_base + A_BYTES
                          + (wn*64 + (lane & 7) + ((lane >> 4) << 3)) * ROW_BYTES
                          + ((lane >> 3) & 1) * 16;

    const int rq = lane >> 2;      // 0..7
    const int cq = (lane & 3) * 2; // 0,2,4,6
    const int NCHUNK = DDIM / KC;  // 16

    #pragma unroll 1
    for (int sub = 0; sub < nsub; sub++) {
        const int cb = cb0 + sub;
        const bool is_diag = (cb == rb);
        const bool is_pos  = (cb == rb + 32);
        const char* gB = (const char*)g_fn
                       + ((size_t)(cb * 128 + rA) * DDIM) * 2 + p16;

        float acc[2][8][4];
        #pragma unroll
        for (int mf = 0; mf < 2; mf++)
            #pragma unroll
            for (int j = 0; j < 8; j++)
                #pragma unroll
                for (int e = 0; e < 4; e++) acc[mf][j][e] = 0.0f;

        __syncthreads();   // protect stage reuse across sub-tiles
        load_halfA(ldst + 0*STAGE_BYTES, gA);
        load_halfB(ldst + 0*STAGE_BYTES, gB);       cp_commit();
        load_halfA(ldst + 1*STAGE_BYTES, gA + 128);
        load_halfB(ldst + 1*STAGE_BYTES, gB + 128); cp_commit();

        for (int kc = 0; kc < NCHUNK; kc++) {
            if (kc < NCHUNK - 1) asm volatile("cp.async.wait_group 1;" ::: "memory");
            else                 asm volatile("cp.async.wait_group 0;" ::: "memory");
            __syncthreads();
            const unsigned sA = a_base + (kc % NSTAGES) * STAGE_BYTES;
            const unsigned sB = b_base + (kc % NSTAGES) * STAGE_BYTES;
            const unsigned pdst = ldst + ((kc + 2) % NSTAGES) * STAGE_BYTES;
            const bool     pf   = (kc + 2 < NCHUNK);

            unsigned a[2][2][4];   // [buf][mf][frag] double-buffered across ks
            #pragma unroll
            for (int mf = 0; mf < 2; mf++)
                ldmatrix_x4(a[0][mf][0], a[0][mf][1], a[0][mf][2], a[0][mf][3],
                            sA + mf * (16 * ROW_BYTES));

            #pragma unroll
            for (int ks = 0; ks < 4; ks++) {
                const int ab = ks & 1;
                unsigned b[2][4];
                ldmatrix_x4(b[0][0], b[0][1], b[0][2], b[0][3], sB + ks * 32);
                if (ks < 3) {
                    #pragma unroll
                    for (int mf = 0; mf < 2; mf++)
                        ldmatrix_x4(a[ab^1][mf][0], a[ab^1][mf][1],
                                    a[ab^1][mf][2], a[ab^1][mf][3],
                                    sA + mf * (16 * ROW_BYTES) + (ks + 1) * 32);
                }
                #pragma unroll
                for (int nf = 0; nf < 4; nf++) {
                    const int cur = nf & 1;
                    if (nf < 3)
                        ldmatrix_x4(b[cur^1][0], b[cur^1][1], b[cur^1][2], b[cur^1][3],
                                    sB + (nf + 1) * (16 * ROW_BYTES) + ks * 32);
                    #pragma unroll
                    for (int mf = 0; mf < 2; mf++) {
                        mma_bf16(acc[mf][2*nf][0],   acc[mf][2*nf][1],
                                 acc[mf][2*nf][2],   acc[mf][2*nf][3],
                                 a[ab][mf][0], a[ab][mf][1], a[ab][mf][2], a[ab][mf][3],
                                 b[cur][0], b[cur][1]);
                        mma_bf16(acc[mf][2*nf+1][0], acc[mf][2*nf+1][1],
                                 acc[mf][2*nf+1][2], acc[mf][2*nf+1][3],
                                 a[ab][mf][0], a[ab][mf][1], a[ab][mf][2], a[ab][mf][3],
                                 b[cur][2], b[cur][3]);
                    }
                }
                // spread prefetch: A-half after ks=0, B-half after ks=1
                if (ks == 0 && pf) load_halfA(pdst, gA + (kc + 2) * 128);
                if (ks == 1 && pf) { load_halfB(pdst, gB + (kc + 2) * 128); cp_commit(); }
            }
        }

        // ---------------- epilogue ----------------
        float rs[2][2] = {{0.f,0.f},{0.f,0.f}};
        float cs[8][2];
        #pragma unroll
        for (int j = 0; j < 8; j++) { cs[j][0] = 0.f; cs[j][1] = 0.f; }

        #pragma unroll
        for (int mf = 0; mf < 2; mf++) {
            #pragma unroll
            for (int j = 0; j < 8; j++) {
                #pragma unroll
                for (int e = 0; e < 4; e++) {
                    float a  = acc[mf][j][e];
                    int r_local = wm*32 + mf*16 + rq + ((e & 2) ? 8 : 0);
                    int c_local = wn*64 + j*8 + cq + (e & 1);
                    float ev = fexp2f(a * Y_SCALE);
                    if (is_diag && r_local == c_local) ev = 0.0f;
                    rs[mf][e >> 1] += ev;
                    cs[j][e & 1]   += ev;
                    if (is_pos && r_local == c_local) {
                        float pv = a * INVT;
                        atomicAdd(&g_pos[rb*128 + r_local], pv);
                        atomicAdd(&g_pos[cb*128 + c_local], pv);
                    }
                }
            }
        }

        #pragma unroll
        for (int mf = 0; mf < 2; mf++) {
            #pragma unroll
            for (int h = 0; h < 2; h++) {
                float v = rs[mf][h];
                v += __shfl_xor_sync(0xFFFFFFFFu, v, 1);
                v += __shfl_xor_sync(0xFFFFFFFFu, v, 2);
                if ((lane & 3) == 0)
                    atomicAdd(&g_rowsum[rb*128 + wm*32 + mf*16 + rq + h*8], v);
            }
        }

        if (!is_diag) {
            #pragma unroll
            for (int j = 0; j < 8; j++) {
                #pragma unroll
                for (int par = 0; par < 2; par++) {
                    float v = cs[j][par];
                    v += __shfl_xor_sync(0xFFFFFFFFu, v, 4);
                    v += __shfl_xor_sync(0xFFFFFFFFu, v, 8);
                    v += __shfl_xor_sync(0xFFFFFFFFu, v, 16);
                    if (lane < 4)
                        atomicAdd(&g_rowsum[cb*128 + wn*64 + j*8 + lane*2 + par], v);
                }
            }
        }
    }
}

// ---------------------------------------------------------------------------
// Kernel 3: loss partials -> atomicAdd into out (out zeroed by norm_kernel)
// ---------------------------------------------------------------------------
__global__ void __launch_bounds__(256) loss_kernel(float* __restrict__ out) {
    const int base = blockIdx.x * (NROWS / 32);
    float s = 0.0f;
    for (int i = threadIdx.x; i < NROWS / 32; i += 256) {
        int r = base + i;
        s += logf(g_rowsum[r]) - g_pos[r];
    }
    #pragma unroll
    for (int o = 16; o; o >>= 1) s += __shfl_xor_sync(0xFFFFFFFFu, s, o);
    __shared__ float red[8];
    if ((threadIdx.x & 31) == 0) red[threadIdx.x >> 5] = s;
    __syncthreads();
    if (threadIdx.x == 0) {
        float tot = red[0]+red[1]+red[2]+red[3]+red[4]+red[5]+red[6]+red[7];
        atomicAdd(out, tot * (1.0f / (float)NROWS));
    }
}

// ---------------------------------------------------------------------------
extern "C" void kernel_launch(void* const* d_in, const int* in_sizes, int n_in,
                              void* d_out, int out_size) {
    const float* v1 = (const float*)d_in[0];
    const float* v2 = (const float*)d_in[1];
    float* out = (float*)d_out;

    cudaFuncSetAttribute(simexp_kernel,
                         cudaFuncAttributeMaxDynamicSharedMemorySize, SMEM_TOTAL);

    norm_kernel<<<NROWS / 4, 128>>>(v1, v2, out);
    simexp_kernel<<<NJOBS, 256, SMEM_TOTAL>>>();
    loss_kernel<<<32, 256>>>(out);
}